// round 2
// baseline (speedup 1.0000x reference)
#include <cuda_runtime.h>
#include <math.h>

// Problem constants (fixed-shape problem)
#define NUM_G   1024
#define NPG     256
#define INF     768      // in feats
#define HID     128
#define NC      2

// Scratch (allocation-free rule: __device__ globals)
__device__ float g_Xsum[NUM_G * INF];   // per-graph column sums of x  (3 MB)
__device__ float g_hp[HID];             // prompt @ W1
__device__ float g_hc01[HID];           // (c0 + c1) @ W1
__device__ float g_M[HID * 2];          // W2 @ Wfc
__device__ float g_C[4];                // constant logit offsets C[k][c]

__device__ __forceinline__ float norm_a() { return rsqrtf(518.0f); }      // dinv_leaf * dinv_prompt
__device__ __forceinline__ float norm_p() { return 1.0f / 259.0f; }       // dinv_prompt^2

// ---------------------------------------------------------------------------
// K0: setup constants. 1 block, 128 threads.
// ---------------------------------------------------------------------------
__global__ void setup_kernel(const float* __restrict__ prompt,
                             const float* __restrict__ cls,     // [2, 768]
                             const float* __restrict__ W1,      // [768, 128]
                             const float* __restrict__ b1,      // [128]
                             const float* __restrict__ W2,      // [128, 128]
                             const float* __restrict__ b2,      // [128]
                             const float* __restrict__ Wfc,     // [128, 2]
                             const float* __restrict__ bfc)     // [2]
{
    const int j = threadIdx.x;          // 0..127
    const float A = norm_a();

    // h_p, h_c0, h_c1 : column j of (vec @ W1)
    float hp = 0.f, h0 = 0.f, h1 = 0.f;
    for (int k = 0; k < INF; k++) {
        float w = __ldg(&W1[k * HID + j]);
        hp += prompt[k] * w;
        h0 += cls[k] * w;
        h1 += cls[INF + k] * w;
    }
    g_hp[j]   = hp;
    g_hc01[j] = h0 + h1;

    // layer-1 class-node outputs (graph-independent), after relu
    float rc0 = fmaxf(A * hp + 0.5f * h0 + b1[j], 0.f);
    float rc1 = fmaxf(A * hp + 0.5f * h1 + b1[j], 0.f);

    // M = W2 @ Wfc  (row j)
    float m0 = 0.f, m1 = 0.f;
    for (int k = 0; k < HID; k++) {
        float w2 = W2[j * HID + k];
        m0 += w2 * Wfc[k * 2 + 0];
        m1 += w2 * Wfc[k * 2 + 1];
    }
    g_M[j * 2 + 0] = m0;
    g_M[j * 2 + 1] = m1;

    // C[k][c] = 0.5 * (rc_k . M[:,c]) + (b2 @ Wfc)[c] + bfc[c]
    float v[6];
    v[0] = 0.5f * rc0 * m0;  v[1] = 0.5f * rc0 * m1;
    v[2] = 0.5f * rc1 * m0;  v[3] = 0.5f * rc1 * m1;
    v[4] = b2[j] * Wfc[j * 2 + 0];
    v[5] = b2[j] * Wfc[j * 2 + 1];

    const int lane = j & 31, warp = j >> 5;
    #pragma unroll
    for (int o = 16; o > 0; o >>= 1)
        #pragma unroll
        for (int i = 0; i < 6; i++)
            v[i] += __shfl_down_sync(0xffffffffu, v[i], o);

    __shared__ float sred[4][6];
    if (lane == 0)
        for (int i = 0; i < 6; i++) sred[warp][i] = v[i];
    __syncthreads();

    if (j == 0) {
        float t[6];
        for (int i = 0; i < 6; i++)
            t[i] = sred[0][i] + sred[1][i] + sred[2][i] + sred[3][i];
        g_C[0] = t[0] + t[4] + bfc[0];   // k=0, c=0
        g_C[1] = t[1] + t[5] + bfc[1];   // k=0, c=1
        g_C[2] = t[2] + t[4] + bfc[0];   // k=1, c=0
        g_C[3] = t[3] + t[5] + bfc[1];   // k=1, c=1
    }
}

// ---------------------------------------------------------------------------
// K1: per-graph column sums of x. THE hot kernel: streams 805 MB.
// grid = 1024 blocks (one per graph), 192 threads (one float4 column each).
// ---------------------------------------------------------------------------
__global__ void __launch_bounds__(192) sum_kernel(const float* __restrict__ x)
{
    const int g = blockIdx.x;
    const int c = threadIdx.x;                   // 0..191 float4 columns
    const float4* base = (const float4*)x + (size_t)g * NPG * 192 + c;

    float4 acc = make_float4(0.f, 0.f, 0.f, 0.f);
    #pragma unroll 8
    for (int r = 0; r < NPG; r++) {
        float4 v = __ldcs(base + (size_t)r * 192);  // streaming: no reuse
        acc.x += v.x; acc.y += v.y; acc.z += v.z; acc.w += v.w;
    }
    ((float4*)g_Xsum)[(size_t)g * 192 + c] = acc;
}

// ---------------------------------------------------------------------------
// K2: S = Xsum @ W1, fused epilogue -> log_softmax output.
// grid = 128 blocks (8 graphs each), 256 threads.
// Thread (j = tid&127, half = tid>>7) computes S[g][j] for 4 graphs.
// ---------------------------------------------------------------------------
#define GPB 8
__global__ void __launch_bounds__(256) final_kernel(const float* __restrict__ W1,
                                                    const float* __restrict__ b1,
                                                    float* __restrict__ out)
{
    __shared__ float4 xs4[GPB][192];             // 24 KB
    __shared__ float sred[8][4][2];

    const int tid = threadIdx.x;
    const int g0 = blockIdx.x * GPB;

    // stage Xsum rows for this block's 8 graphs
    const float4* X4 = (const float4*)g_Xsum;
    for (int i = tid; i < GPB * 192; i += 256)
        xs4[i / 192][i % 192] = X4[(size_t)(g0 + i / 192) * 192 + (i % 192)];
    __syncthreads();

    const int j    = tid & 127;
    const int half = tid >> 7;                   // graphs half*4 .. half*4+3

    float acc[4] = {0.f, 0.f, 0.f, 0.f};
    #pragma unroll 2
    for (int k4 = 0; k4 < 192; k4++) {
        const int k = k4 * 4;
        float w0 = __ldg(&W1[(k + 0) * HID + j]);
        float w1 = __ldg(&W1[(k + 1) * HID + j]);
        float w2 = __ldg(&W1[(k + 2) * HID + j]);
        float w3 = __ldg(&W1[(k + 3) * HID + j]);
        #pragma unroll
        for (int gi = 0; gi < 4; gi++) {
            float4 xv = xs4[half * 4 + gi][k4];  // warp-uniform broadcast
            acc[gi] += xv.x * w0 + xv.y * w1 + xv.z * w2 + xv.w * w3;
        }
    }

    // epilogue: r_p = relu(a*(S + hc01) + (1/259)*hp + b1);  w_c = r_p . M[:,c]
    const float A  = norm_a();
    const float BP = norm_p();
    const float hp = g_hp[j], hc = g_hc01[j], bb = b1[j];
    const float m0 = g_M[j * 2 + 0], m1 = g_M[j * 2 + 1];

    float p0[4], p1[4];
    #pragma unroll
    for (int gi = 0; gi < 4; gi++) {
        float t = A * (acc[gi] + hc) + BP * hp + bb;
        float r = fmaxf(t, 0.f);
        p0[gi] = r * m0;
        p1[gi] = r * m1;
    }

    #pragma unroll
    for (int o = 16; o > 0; o >>= 1)
        #pragma unroll
        for (int gi = 0; gi < 4; gi++) {
            p0[gi] += __shfl_down_sync(0xffffffffu, p0[gi], o);
            p1[gi] += __shfl_down_sync(0xffffffffu, p1[gi], o);
        }

    const int lane = tid & 31, warp = tid >> 5;
    if (lane == 0)
        #pragma unroll
        for (int gi = 0; gi < 4; gi++) {
            sred[warp][gi][0] = p0[gi];
            sred[warp][gi][1] = p1[gi];
        }
    __syncthreads();

    if (tid < GPB) {
        const int gl = tid, hf = gl >> 2, gi = gl & 3;
        float W0 = 0.f, W1v = 0.f;
        #pragma unroll
        for (int w = 0; w < 4; w++) {
            W0  += sred[hf * 4 + w][gi][0];
            W1v += sred[hf * 4 + w][gi][1];
        }
        const int base = (g0 + gl) * 4;          // rows (2g+k), 2 cols each
        #pragma unroll
        for (int k = 0; k < 2; k++) {
            float l0 = A * W0  + g_C[k * 2 + 0];
            float l1 = A * W1v + g_C[k * 2 + 1];
            float mx = fmaxf(l0, l1);
            float lse = mx + logf(expf(l0 - mx) + expf(l1 - mx));
            out[base + 2 * k + 0] = l0 - lse;
            out[base + 2 * k + 1] = l1 - lse;
        }
    }
}

// ---------------------------------------------------------------------------
extern "C" void kernel_launch(void* const* d_in, const int* in_sizes, int n_in,
                              void* d_out, int out_size)
{
    const float* x      = (const float*)d_in[0];
    const float* prompt = (const float*)d_in[1];
    const float* cls    = (const float*)d_in[2];
    const float* W1     = (const float*)d_in[3];
    const float* b1     = (const float*)d_in[4];
    const float* W2     = (const float*)d_in[5];
    const float* b2     = (const float*)d_in[6];
    const float* Wfc    = (const float*)d_in[7];
    const float* bfc    = (const float*)d_in[8];
    float* out = (float*)d_out;

    setup_kernel<<<1, 128>>>(prompt, cls, W1, b1, W2, b2, Wfc, bfc);
    sum_kernel<<<NUM_G, 192>>>(x);
    final_kernel<<<NUM_G / GPB, 256>>>(W1, b1, out);
}

// round 3
// speedup vs baseline: 1.2441x; 1.2441x over previous
#include <cuda_runtime.h>
#include <math.h>

// Problem constants (fixed-shape problem)
#define NUM_G   1024
#define NPG     256
#define INF     768      // in feats
#define HID     128
#define NC      2

// Scratch (allocation-free rule: __device__ globals)
__device__ float g_Xsum[NUM_G * INF];   // per-graph column sums of x  (3 MB)
__device__ float g_hp[HID];             // prompt @ W1
__device__ float g_h0[HID];             // class0 @ W1
__device__ float g_h1[HID];             // class1 @ W1
__device__ float g_hc01[HID];           // h0 + h1
__device__ float g_M[HID * 2];          // W2 @ Wfc
__device__ float g_C[4];                // constant logit offsets C[k][c]

__device__ __forceinline__ float norm_a() { return rsqrtf(518.0f); }      // dinv_leaf * dinv_prompt
__device__ __forceinline__ float norm_p() { return 1.0f / 259.0f; }       // dinv_prompt^2

// ---------------------------------------------------------------------------
// setup_a: one block per output column j (128 blocks, 256 threads).
// Computes g_hp[j], g_h0[j], g_h1[j], g_M[j][:].
// ---------------------------------------------------------------------------
__global__ void __launch_bounds__(256) setup_a(const float* __restrict__ prompt,
                                               const float* __restrict__ cls,   // [2,768]
                                               const float* __restrict__ W1,    // [768,128]
                                               const float* __restrict__ W2,    // [128,128]
                                               const float* __restrict__ Wfc)   // [128,2]
{
    const int j = blockIdx.x;            // 0..127
    const int t = threadIdx.x;           // 0..255

    float v[5] = {0.f, 0.f, 0.f, 0.f, 0.f};   // hp, h0, h1, m0, m1

    #pragma unroll
    for (int i = 0; i < 3; i++) {
        const int k = t + i * 256;
        float w = __ldg(&W1[k * HID + j]);
        v[0] += __ldg(&prompt[k])      * w;
        v[1] += __ldg(&cls[k])         * w;
        v[2] += __ldg(&cls[INF + k])   * w;
    }
    if (t < HID) {
        float w2 = __ldg(&W2[j * HID + t]);
        v[3] = w2 * __ldg(&Wfc[t * 2 + 0]);
        v[4] = w2 * __ldg(&Wfc[t * 2 + 1]);
    }

    // reduce 5 values over 256 threads
    #pragma unroll
    for (int o = 16; o > 0; o >>= 1)
        #pragma unroll
        for (int i = 0; i < 5; i++)
            v[i] += __shfl_down_sync(0xffffffffu, v[i], o);

    __shared__ float sred[8][5];
    const int lane = t & 31, warp = t >> 5;
    if (lane == 0)
        #pragma unroll
        for (int i = 0; i < 5; i++) sred[warp][i] = v[i];
    __syncthreads();

    if (t == 0) {
        float s[5];
        #pragma unroll
        for (int i = 0; i < 5; i++) {
            s[i] = sred[0][i];
            #pragma unroll
            for (int w = 1; w < 8; w++) s[i] += sred[w][i];
        }
        g_hp[j]        = s[0];
        g_h0[j]        = s[1];
        g_h1[j]        = s[2];
        g_hc01[j]      = s[1] + s[2];
        g_M[j * 2 + 0] = s[3];
        g_M[j * 2 + 1] = s[4];
    }
}

// ---------------------------------------------------------------------------
// setup_b: tiny finisher. 1 block, 128 threads. Computes g_C from the 128-wide
// precomputed vectors (all reads are small / L2-resident).
// ---------------------------------------------------------------------------
__global__ void setup_b(const float* __restrict__ b1,
                        const float* __restrict__ b2,
                        const float* __restrict__ Wfc,
                        const float* __restrict__ bfc)
{
    const int j = threadIdx.x;           // 0..127
    const float A = norm_a();

    const float hp = g_hp[j], h0 = g_h0[j], h1 = g_h1[j];
    const float m0 = g_M[j * 2 + 0], m1 = g_M[j * 2 + 1];

    // layer-1 class-node outputs (graph-independent), after relu
    float rc0 = fmaxf(A * hp + 0.5f * h0 + b1[j], 0.f);
    float rc1 = fmaxf(A * hp + 0.5f * h1 + b1[j], 0.f);

    float v[6];
    v[0] = 0.5f * rc0 * m0;  v[1] = 0.5f * rc0 * m1;
    v[2] = 0.5f * rc1 * m0;  v[3] = 0.5f * rc1 * m1;
    v[4] = b2[j] * Wfc[j * 2 + 0];
    v[5] = b2[j] * Wfc[j * 2 + 1];

    const int lane = j & 31, warp = j >> 5;
    #pragma unroll
    for (int o = 16; o > 0; o >>= 1)
        #pragma unroll
        for (int i = 0; i < 6; i++)
            v[i] += __shfl_down_sync(0xffffffffu, v[i], o);

    __shared__ float sred[4][6];
    if (lane == 0)
        for (int i = 0; i < 6; i++) sred[warp][i] = v[i];
    __syncthreads();

    if (j == 0) {
        float t[6];
        for (int i = 0; i < 6; i++)
            t[i] = sred[0][i] + sred[1][i] + sred[2][i] + sred[3][i];
        g_C[0] = t[0] + t[4] + bfc[0];   // k=0, c=0
        g_C[1] = t[1] + t[5] + bfc[1];   // k=0, c=1
        g_C[2] = t[2] + t[4] + bfc[0];   // k=1, c=0
        g_C[3] = t[3] + t[5] + bfc[1];   // k=1, c=1
    }
}

// ---------------------------------------------------------------------------
// K1: per-graph column sums of x. THE hot kernel: streams 805 MB at HBM peak.
// grid = 1024 blocks (one per graph), 192 threads (one float4 column each).
// ---------------------------------------------------------------------------
__global__ void __launch_bounds__(192) sum_kernel(const float* __restrict__ x)
{
    const int g = blockIdx.x;
    const int c = threadIdx.x;                   // 0..191 float4 columns
    const float4* base = (const float4*)x + (size_t)g * NPG * 192 + c;

    float4 acc = make_float4(0.f, 0.f, 0.f, 0.f);
    #pragma unroll 8
    for (int r = 0; r < NPG; r++) {
        float4 v = __ldcs(base + (size_t)r * 192);  // streaming: no reuse
        acc.x += v.x; acc.y += v.y; acc.z += v.z; acc.w += v.w;
    }
    ((float4*)g_Xsum)[(size_t)g * 192 + c] = acc;
}

// ---------------------------------------------------------------------------
// K2: S = Xsum @ W1, fused epilogue -> log_softmax output.
// grid = 128 blocks (8 graphs each), 256 threads.
// ---------------------------------------------------------------------------
#define GPB 8
__global__ void __launch_bounds__(256) final_kernel(const float* __restrict__ W1,
                                                    const float* __restrict__ b1,
                                                    float* __restrict__ out)
{
    __shared__ float4 xs4[GPB][192];             // 24 KB
    __shared__ float sred[8][4][2];

    const int tid = threadIdx.x;
    const int g0 = blockIdx.x * GPB;

    // stage Xsum rows for this block's 8 graphs
    const float4* X4 = (const float4*)g_Xsum;
    for (int i = tid; i < GPB * 192; i += 256)
        xs4[i / 192][i % 192] = X4[(size_t)(g0 + i / 192) * 192 + (i % 192)];
    __syncthreads();

    const int j    = tid & 127;
    const int half = tid >> 7;                   // graphs half*4 .. half*4+3

    float acc[4] = {0.f, 0.f, 0.f, 0.f};
    #pragma unroll 2
    for (int k4 = 0; k4 < 192; k4++) {
        const int k = k4 * 4;
        float w0 = __ldg(&W1[(k + 0) * HID + j]);
        float w1 = __ldg(&W1[(k + 1) * HID + j]);
        float w2 = __ldg(&W1[(k + 2) * HID + j]);
        float w3 = __ldg(&W1[(k + 3) * HID + j]);
        #pragma unroll
        for (int gi = 0; gi < 4; gi++) {
            float4 xv = xs4[half * 4 + gi][k4];  // warp-uniform broadcast
            acc[gi] += xv.x * w0 + xv.y * w1 + xv.z * w2 + xv.w * w3;
        }
    }

    // epilogue: r_p = relu(a*(S + hc01) + (1/259)*hp + b1);  w_c = r_p . M[:,c]
    const float A  = norm_a();
    const float BP = norm_p();
    const float hp = g_hp[j], hc = g_hc01[j], bb = b1[j];
    const float m0 = g_M[j * 2 + 0], m1 = g_M[j * 2 + 1];

    float p0[4], p1[4];
    #pragma unroll
    for (int gi = 0; gi < 4; gi++) {
        float t = A * (acc[gi] + hc) + BP * hp + bb;
        float r = fmaxf(t, 0.f);
        p0[gi] = r * m0;
        p1[gi] = r * m1;
    }

    #pragma unroll
    for (int o = 16; o > 0; o >>= 1)
        #pragma unroll
        for (int gi = 0; gi < 4; gi++) {
            p0[gi] += __shfl_down_sync(0xffffffffu, p0[gi], o);
            p1[gi] += __shfl_down_sync(0xffffffffu, p1[gi], o);
        }

    const int lane = tid & 31, warp = tid >> 5;
    if (lane == 0)
        #pragma unroll
        for (int gi = 0; gi < 4; gi++) {
            sred[warp][gi][0] = p0[gi];
            sred[warp][gi][1] = p1[gi];
        }
    __syncthreads();

    if (tid < GPB) {
        const int gl = tid, hf = gl >> 2, gi = gl & 3;
        float W0 = 0.f, W1v = 0.f;
        #pragma unroll
        for (int w = 0; w < 4; w++) {
            W0  += sred[hf * 4 + w][gi][0];
            W1v += sred[hf * 4 + w][gi][1];
        }
        const int base = (g0 + gl) * 4;          // rows (2g+k), 2 cols each
        #pragma unroll
        for (int k = 0; k < 2; k++) {
            float l0 = A * W0  + g_C[k * 2 + 0];
            float l1 = A * W1v + g_C[k * 2 + 1];
            float mx = fmaxf(l0, l1);
            float lse = mx + logf(expf(l0 - mx) + expf(l1 - mx));
            out[base + 2 * k + 0] = l0 - lse;
            out[base + 2 * k + 1] = l1 - lse;
        }
    }
}

// ---------------------------------------------------------------------------
extern "C" void kernel_launch(void* const* d_in, const int* in_sizes, int n_in,
                              void* d_out, int out_size)
{
    const float* x      = (const float*)d_in[0];
    const float* prompt = (const float*)d_in[1];
    const float* cls    = (const float*)d_in[2];
    const float* W1     = (const float*)d_in[3];
    const float* b1     = (const float*)d_in[4];
    const float* W2     = (const float*)d_in[5];
    const float* b2     = (const float*)d_in[6];
    const float* Wfc    = (const float*)d_in[7];
    const float* bfc    = (const float*)d_in[8];
    float* out = (float*)d_out;

    setup_a<<<HID, 256>>>(prompt, cls, W1, W2, Wfc);
    setup_b<<<1, 128>>>(b1, b2, Wfc, bfc);
    sum_kernel<<<NUM_G, 192>>>(x);
    final_kernel<<<NUM_G / GPB, 256>>>(W1, b1, out);
}